// round 1
// baseline (speedup 1.0000x reference)
#include <cuda_runtime.h>
#include <math.h>

#define N_NODES 100000
#define N_EDGES 50000
#define D 128

// Scratch (allocation-free rule: __device__ globals)
__device__ float g_Xp[(size_t)N_NODES * D];   // 51.2 MB: X @ W
__device__ float g_Xe[(size_t)N_EDGES * D];   // 25.6 MB: per-edge sums

// ---------------------------------------------------------------------------
// K0: zero g_Xe and d_out (d_out accumulates Xv)
// ---------------------------------------------------------------------------
__global__ void zero_kernel(float4* __restrict__ out, int n_out4) {
    int tid0 = blockIdx.x * blockDim.x + threadIdx.x;
    int stride = gridDim.x * blockDim.x;
    float4 z = make_float4(0.f, 0.f, 0.f, 0.f);
    const int ne4 = (N_EDGES * D) / 4;
    float4* xe4 = (float4*)g_Xe;
    for (int i = tid0; i < ne4; i += stride) xe4[i] = z;
    for (int i = tid0; i < n_out4; i += stride) out[i] = z;
}

// ---------------------------------------------------------------------------
// K1: Xp = X @ W   (fp32, BM=128 BN=128 BK=16, 8x8 per thread, 256 threads)
// ---------------------------------------------------------------------------
#define BM 128
#define BN 128
#define BK 16

__global__ __launch_bounds__(256) void gemm_kernel(
    const float* __restrict__ X, const float* __restrict__ W, int M)
{
    __shared__ float As[BK][BM + 4];   // +4 keeps 16B alignment, reduces conflicts
    __shared__ float Bs[BK][BN];

    int tid = threadIdx.x;
    int tx = tid & 15;    // 0..15 -> 8 output cols each
    int ty = tid >> 4;    // 0..15 -> 8 output rows each
    int row0 = blockIdx.x * BM;

    float acc[8][8];
#pragma unroll
    for (int i = 0; i < 8; i++)
#pragma unroll
        for (int j = 0; j < 8; j++) acc[i][j] = 0.f;

    for (int k0 = 0; k0 < D; k0 += BK) {
        // Load A tile: 128 rows x 16 k  (512 float4, 2 per thread)
#pragma unroll
        for (int l = 0; l < 2; l++) {
            int idx = tid * 2 + l;          // 0..511
            int m   = idx >> 2;             // 0..127
            int kq  = (idx & 3) * 4;        // 0,4,8,12
            int gm  = row0 + m;
            float4 av = (gm < M) ? *(const float4*)(X + (size_t)gm * D + k0 + kq)
                                 : make_float4(0.f, 0.f, 0.f, 0.f);
            As[kq + 0][m] = av.x;
            As[kq + 1][m] = av.y;
            As[kq + 2][m] = av.z;
            As[kq + 3][m] = av.w;
        }
        // Load B tile: 16 k x 128 cols (512 float4, 2 per thread)
#pragma unroll
        for (int l = 0; l < 2; l++) {
            int idx = tid * 2 + l;          // 0..511
            int kr  = idx >> 5;             // 0..15
            int n4  = (idx & 31) * 4;       // 0..124
            *(float4*)&Bs[kr][n4] = *(const float4*)(W + (size_t)(k0 + kr) * D + n4);
        }
        __syncthreads();

#pragma unroll
        for (int k = 0; k < BK; k++) {
            float a[8], b[8];
            *(float4*)(a + 0) = *(const float4*)&As[k][ty * 8 + 0];
            *(float4*)(a + 4) = *(const float4*)&As[k][ty * 8 + 4];
            *(float4*)(b + 0) = *(const float4*)&Bs[k][tx * 8 + 0];
            *(float4*)(b + 4) = *(const float4*)&Bs[k][tx * 8 + 4];
#pragma unroll
            for (int i = 0; i < 8; i++)
#pragma unroll
                for (int j = 0; j < 8; j++)
                    acc[i][j] = fmaf(a[i], b[j], acc[i][j]);
        }
        __syncthreads();
    }

#pragma unroll
    for (int i = 0; i < 8; i++) {
        int gm = row0 + ty * 8 + i;
        if (gm < M) {
            float* p = g_Xp + (size_t)gm * D + tx * 8;
            *(float4*)(p + 0) = make_float4(acc[i][0], acc[i][1], acc[i][2], acc[i][3]);
            *(float4*)(p + 4) = make_float4(acc[i][4], acc[i][5], acc[i][6], acc[i][7]);
        }
    }
}

// ---------------------------------------------------------------------------
// 128-bit no-return global reduction (sm_90+)
// ---------------------------------------------------------------------------
__device__ __forceinline__ void red_add_v4(float* dst, float4 v) {
    asm volatile("red.global.add.v4.f32 [%0], {%1, %2, %3, %4};"
                 :: "l"(dst), "f"(v.x), "f"(v.y), "f"(v.z), "f"(v.w)
                 : "memory");
}

// ---------------------------------------------------------------------------
// K2: Xe[edges[i]] += Xp[vertex[i]]   (one warp per incidence entry)
// ---------------------------------------------------------------------------
__global__ __launch_bounds__(256) void scatter_v2e_kernel(
    const int* __restrict__ vertex, const int* __restrict__ edges, int nnz)
{
    int g = blockIdx.x * blockDim.x + threadIdx.x;
    int i = g >> 5;
    if (i >= nnz) return;
    int lane = g & 31;
    int v = __ldg(vertex + i);   // warp-uniform broadcast load
    int e = __ldg(edges + i);
    float4 val = __ldg((const float4*)(g_Xp + (size_t)v * D) + lane);
    red_add_v4(g_Xe + (size_t)e * D + lane * 4, val);
}

// ---------------------------------------------------------------------------
// K3: out[vertex[i]] += Xe[edges[i]]   (out pre-zeroed)
// ---------------------------------------------------------------------------
__global__ __launch_bounds__(256) void scatter_e2v_kernel(
    const int* __restrict__ vertex, const int* __restrict__ edges, int nnz,
    float* __restrict__ out)
{
    int g = blockIdx.x * blockDim.x + threadIdx.x;
    int i = g >> 5;
    if (i >= nnz) return;
    int lane = g & 31;
    int v = __ldg(vertex + i);
    int e = __ldg(edges + i);
    float4 val = __ldg((const float4*)(g_Xe + (size_t)e * D) + lane);
    red_add_v4(out + (size_t)v * D + lane * 4, val);
}

// ---------------------------------------------------------------------------
// K4: out = gelu((1+eps)*Xp + out)   (exact erf)
// ---------------------------------------------------------------------------
__device__ __forceinline__ float gelu_exact(float x) {
    return 0.5f * x * (1.0f + erff(x * 0.70710678118654752440f));
}

__global__ __launch_bounds__(256) void finalize_kernel(
    float* __restrict__ out, const float* __restrict__ eps, int n4)
{
    int i = blockIdx.x * blockDim.x + threadIdx.x;
    if (i >= n4) return;
    float s = 1.0f + __ldg(eps);
    float4 p = ((const float4*)g_Xp)[i];
    float4 a = ((float4*)out)[i];
    float4 r;
    r.x = gelu_exact(fmaf(s, p.x, a.x));
    r.y = gelu_exact(fmaf(s, p.y, a.y));
    r.z = gelu_exact(fmaf(s, p.z, a.z));
    r.w = gelu_exact(fmaf(s, p.w, a.w));
    ((float4*)out)[i] = r;
}

// ---------------------------------------------------------------------------
// Launch
// ---------------------------------------------------------------------------
extern "C" void kernel_launch(void* const* d_in, const int* in_sizes, int n_in,
                              void* d_out, int out_size)
{
    const float* X      = (const float*)d_in[0];   // [N, 128]
    const float* W      = (const float*)d_in[1];   // [128, 128]
    const float* eps    = (const float*)d_in[2];   // [1]
    const int*   vertex = (const int*)d_in[3];     // [nnz]
    const int*   edges  = (const int*)d_in[4];     // [nnz]
    float*       out    = (float*)d_out;           // [N, 128]

    int nnz = in_sizes[3];
    int M   = in_sizes[0] / D;
    int n_out4 = out_size / 4;

    zero_kernel<<<4096, 256>>>((float4*)out, n_out4);

    int gemm_blocks = (M + BM - 1) / BM;
    gemm_kernel<<<gemm_blocks, 256>>>(X, W, M);

    long long sthreads = (long long)nnz * 32;
    int sblocks = (int)((sthreads + 255) / 256);
    scatter_v2e_kernel<<<sblocks, 256>>>(vertex, edges, nnz);
    scatter_e2v_kernel<<<sblocks, 256>>>(vertex, edges, nnz, out);

    finalize_kernel<<<(n_out4 + 255) / 256, 256>>>(out, eps, n_out4);
}

// round 2
// speedup vs baseline: 1.7664x; 1.7664x over previous
#include <cuda_runtime.h>
#include <math.h>

#define N_NODES 100000
#define N_EDGES 50000
#define D 128
#define MAX_NNZ 1600000
#define T_CNT (N_EDGES + N_NODES)          // 150000 concatenated counters
#define SCAN_CHUNK 1024
#define SCAN_NB ((T_CNT + SCAN_CHUNK - 1) / SCAN_CHUNK)   // 147

// ---------------------------------------------------------------------------
// Device-global scratch (allocation-free rule)
// ---------------------------------------------------------------------------
__device__ float g_Xp[(size_t)N_NODES * D];    // 51.2 MB: X @ W
__device__ float g_Xe[(size_t)N_EDGES * D];    // 25.6 MB: per-edge sums
__device__ int   g_cnt[T_CNT];                 // [edge counts | node counts]
__device__ int   g_off[T_CNT + 1];             // exclusive scan of g_cnt
__device__ int   g_cur[T_CNT];                 // fill cursors
__device__ int   g_bsum[SCAN_NB];              // scan block sums
__device__ int   g_list[2 * MAX_NNZ];          // [vlist by edge | elist by node]

// ---------------------------------------------------------------------------
// K0: zero counters
// ---------------------------------------------------------------------------
__global__ void zero_cnt_kernel() {
    int i = blockIdx.x * blockDim.x + threadIdx.x;
    if (i < T_CNT) g_cnt[i] = 0;
}

// ---------------------------------------------------------------------------
// K1: histogram of edges and vertices
// ---------------------------------------------------------------------------
__global__ __launch_bounds__(256) void hist_kernel(
    const int* __restrict__ vertex, const int* __restrict__ edges, int nnz)
{
    int i = blockIdx.x * blockDim.x + threadIdx.x;
    if (i >= nnz) return;
    atomicAdd(&g_cnt[edges[i]], 1);
    atomicAdd(&g_cnt[N_EDGES + vertex[i]], 1);
}

// ---------------------------------------------------------------------------
// K2a/b/c: exclusive scan over g_cnt -> g_off (3-pass)
// ---------------------------------------------------------------------------
__global__ __launch_bounds__(1024) void scan1_kernel() {
    int b = blockIdx.x;
    int i = b * SCAN_CHUNK + threadIdx.x;
    int v = (i < T_CNT) ? g_cnt[i] : 0;
    int lane = threadIdx.x & 31, wid = threadIdx.x >> 5;
    int x = v;
#pragma unroll
    for (int o = 1; o < 32; o <<= 1) {
        int y = __shfl_up_sync(0xffffffffu, x, o);
        if (lane >= o) x += y;
    }
    __shared__ int wsum[32];
    if (lane == 31) wsum[wid] = x;
    __syncthreads();
    if (wid == 0) {
        int w = wsum[lane];
#pragma unroll
        for (int o = 1; o < 32; o <<= 1) {
            int y = __shfl_up_sync(0xffffffffu, w, o);
            if (lane >= o) w += y;
        }
        wsum[lane] = w;
    }
    __syncthreads();
    int base = (wid > 0) ? wsum[wid - 1] : 0;
    int incl = x + base;
    if (i < T_CNT) g_off[i] = incl - v;       // chunk-local exclusive
    if (threadIdx.x == SCAN_CHUNK - 1) g_bsum[b] = incl;
}

__global__ __launch_bounds__(256) void scan2_kernel() {
    __shared__ int s[256];
    int t = threadIdx.x;
    int v = (t < SCAN_NB) ? g_bsum[t] : 0;
    s[t] = v;
    __syncthreads();
    for (int o = 1; o < 256; o <<= 1) {
        int y = (t >= o) ? s[t - o] : 0;
        __syncthreads();
        s[t] += y;
        __syncthreads();
    }
    if (t < SCAN_NB) g_bsum[t] = s[t] - v;    // exclusive
}

__global__ __launch_bounds__(1024) void scan3_kernel(int total) {
    int i = blockIdx.x * SCAN_CHUNK + threadIdx.x;
    if (i < T_CNT) {
        int o = g_off[i] + g_bsum[blockIdx.x];
        g_off[i] = o;
        g_cur[i] = o;
    }
    if (i == 0) g_off[T_CNT] = total;
}

// ---------------------------------------------------------------------------
// K3: fill CSR lists via atomic cursors
// ---------------------------------------------------------------------------
__global__ __launch_bounds__(256) void fill_kernel(
    const int* __restrict__ vertex, const int* __restrict__ edges, int nnz)
{
    int i = blockIdx.x * blockDim.x + threadIdx.x;
    if (i >= nnz) return;
    int e = edges[i], v = vertex[i];
    int p = atomicAdd(&g_cur[e], 1);
    g_list[p] = v;                             // by-edge list of vertices
    int q = atomicAdd(&g_cur[N_EDGES + v], 1);
    g_list[q] = e;                             // by-node list of edges
}

// ---------------------------------------------------------------------------
// K4: Xp = X @ W   (fp32, BM=128 BN=128 BK=16, 8x8 per thread, 256 threads)
// ---------------------------------------------------------------------------
#define BM 128
#define BN 128
#define BK 16

__global__ __launch_bounds__(256) void gemm_kernel(
    const float* __restrict__ X, const float* __restrict__ W, int M)
{
    __shared__ float As[BK][BM + 4];
    __shared__ float Bs[BK][BN];

    int tid = threadIdx.x;
    int tx = tid & 15;
    int ty = tid >> 4;
    int row0 = blockIdx.x * BM;

    float acc[8][8];
#pragma unroll
    for (int i = 0; i < 8; i++)
#pragma unroll
        for (int j = 0; j < 8; j++) acc[i][j] = 0.f;

    for (int k0 = 0; k0 < D; k0 += BK) {
#pragma unroll
        for (int l = 0; l < 2; l++) {
            int idx = tid * 2 + l;
            int m   = idx >> 2;
            int kq  = (idx & 3) * 4;
            int gm  = row0 + m;
            float4 av = (gm < M) ? *(const float4*)(X + (size_t)gm * D + k0 + kq)
                                 : make_float4(0.f, 0.f, 0.f, 0.f);
            As[kq + 0][m] = av.x;
            As[kq + 1][m] = av.y;
            As[kq + 2][m] = av.z;
            As[kq + 3][m] = av.w;
        }
#pragma unroll
        for (int l = 0; l < 2; l++) {
            int idx = tid * 2 + l;
            int kr  = idx >> 5;
            int n4  = (idx & 31) * 4;
            *(float4*)&Bs[kr][n4] = *(const float4*)(W + (size_t)(k0 + kr) * D + n4);
        }
        __syncthreads();

#pragma unroll
        for (int k = 0; k < BK; k++) {
            float a[8], b[8];
            *(float4*)(a + 0) = *(const float4*)&As[k][ty * 8 + 0];
            *(float4*)(a + 4) = *(const float4*)&As[k][ty * 8 + 4];
            *(float4*)(b + 0) = *(const float4*)&Bs[k][tx * 8 + 0];
            *(float4*)(b + 4) = *(const float4*)&Bs[k][tx * 8 + 4];
#pragma unroll
            for (int i = 0; i < 8; i++)
#pragma unroll
                for (int j = 0; j < 8; j++)
                    acc[i][j] = fmaf(a[i], b[j], acc[i][j]);
        }
        __syncthreads();
    }

#pragma unroll
    for (int i = 0; i < 8; i++) {
        int gm = row0 + ty * 8 + i;
        if (gm < M) {
            float* p = g_Xp + (size_t)gm * D + tx * 8;
            *(float4*)(p + 0) = make_float4(acc[i][0], acc[i][1], acc[i][2], acc[i][3]);
            *(float4*)(p + 4) = make_float4(acc[i][4], acc[i][5], acc[i][6], acc[i][7]);
        }
    }
}

// ---------------------------------------------------------------------------
// Warp segment-sum helper: acc += sum_{j in [start,end)} src4[list[j]*32 + lane]
// ---------------------------------------------------------------------------
__device__ __forceinline__ void warp_segment_sum(
    const float4* __restrict__ src4, int start, int end, int lane, float4& acc)
{
    for (int j = start; j < end; j += 32) {
        int n = end - j;
        int cnt = n < 32 ? n : 32;
        int idx = (lane < cnt) ? __ldg(g_list + j + lane) : 0;
        int t = 0;
        for (; t + 8 <= cnt; t += 8) {
#pragma unroll
            for (int u = 0; u < 8; u++) {
                int r = __shfl_sync(0xffffffffu, idx, t + u);
                float4 val = __ldg(src4 + (size_t)r * 32 + lane);
                acc.x += val.x; acc.y += val.y; acc.z += val.z; acc.w += val.w;
            }
        }
        for (; t < cnt; t++) {
            int r = __shfl_sync(0xffffffffu, idx, t);
            float4 val = __ldg(src4 + (size_t)r * 32 + lane);
            acc.x += val.x; acc.y += val.y; acc.z += val.z; acc.w += val.w;
        }
    }
}

// ---------------------------------------------------------------------------
// K5: Xe[e] = sum over incident vertices of Xp  (warp per edge, no atomics)
// ---------------------------------------------------------------------------
__global__ __launch_bounds__(256) void gather_edge_kernel() {
    int warp = (blockIdx.x * blockDim.x + threadIdx.x) >> 5;
    if (warp >= N_EDGES) return;
    int lane = threadIdx.x & 31;
    int start = g_off[warp];
    int end   = g_off[warp + 1];
    float4 acc = make_float4(0.f, 0.f, 0.f, 0.f);
    warp_segment_sum((const float4*)g_Xp, start, end, lane, acc);
    ((float4*)g_Xe)[(size_t)warp * 32 + lane] = acc;
}

// ---------------------------------------------------------------------------
// K6: out[v] = gelu((1+eps)*Xp[v] + sum over incident edges of Xe)
// ---------------------------------------------------------------------------
__device__ __forceinline__ float gelu_exact(float x) {
    return 0.5f * x * (1.0f + erff(x * 0.70710678118654752440f));
}

__global__ __launch_bounds__(256) void gather_node_kernel(
    float* __restrict__ out, const float* __restrict__ eps, int M)
{
    int warp = (blockIdx.x * blockDim.x + threadIdx.x) >> 5;
    if (warp >= M) return;
    int lane = threadIdx.x & 31;
    int start = g_off[N_EDGES + warp];
    int end   = g_off[N_EDGES + warp + 1];
    float4 acc = make_float4(0.f, 0.f, 0.f, 0.f);
    warp_segment_sum((const float4*)g_Xe, start, end, lane, acc);

    float s = 1.0f + __ldg(eps);
    float4 p = __ldg((const float4*)g_Xp + (size_t)warp * 32 + lane);
    float4 r;
    r.x = gelu_exact(fmaf(s, p.x, acc.x));
    r.y = gelu_exact(fmaf(s, p.y, acc.y));
    r.z = gelu_exact(fmaf(s, p.z, acc.z));
    r.w = gelu_exact(fmaf(s, p.w, acc.w));
    ((float4*)out)[(size_t)warp * 32 + lane] = r;
}

// ---------------------------------------------------------------------------
// Launch
// ---------------------------------------------------------------------------
extern "C" void kernel_launch(void* const* d_in, const int* in_sizes, int n_in,
                              void* d_out, int out_size)
{
    const float* X      = (const float*)d_in[0];   // [N, 128]
    const float* W      = (const float*)d_in[1];   // [128, 128]
    const float* eps    = (const float*)d_in[2];   // [1]
    const int*   vertex = (const int*)d_in[3];     // [nnz]
    const int*   edges  = (const int*)d_in[4];     // [nnz]
    float*       out    = (float*)d_out;           // [N, 128]

    int nnz = in_sizes[3];
    int M   = in_sizes[0] / D;

    // CSR build
    zero_cnt_kernel<<<(T_CNT + 255) / 256, 256>>>();
    hist_kernel<<<(nnz + 255) / 256, 256>>>(vertex, edges, nnz);
    scan1_kernel<<<SCAN_NB, SCAN_CHUNK>>>();
    scan2_kernel<<<1, 256>>>();
    scan3_kernel<<<SCAN_NB, SCAN_CHUNK>>>(2 * nnz);
    fill_kernel<<<(nnz + 255) / 256, 256>>>(vertex, edges, nnz);

    // GEMM
    gemm_kernel<<<(M + BM - 1) / BM, 256>>>(X, W, M);

    // Two gather segment-sum passes (pass 2 fused with GELU finalize)
    gather_edge_kernel<<<(N_EDGES * 32 + 255) / 256, 256>>>();
    gather_node_kernel<<<(M * 32 + 255) / 256, 256>>>(out, eps, M);
}

// round 3
// speedup vs baseline: 1.8795x; 1.0640x over previous
#include <cuda_runtime.h>
#include <cuda_fp16.h>
#include <math.h>

#define N_NODES 100000
#define N_EDGES 50000
#define D 128
#define MAX_NNZ 1600000
#define T_CNT (N_EDGES + N_NODES)
#define SCAN_CHUNK 1024
#define SCAN_NB ((T_CNT + SCAN_CHUNK - 1) / SCAN_CHUNK)

// ---------------------------------------------------------------------------
// Device-global scratch
// ---------------------------------------------------------------------------
__device__ float        g_Xp [(size_t)N_NODES * D];    // fp32 Xp (combine)
__device__ unsigned int g_Xph[(size_t)N_NODES * (D/2)];// fp16 Xp (gather src)
__device__ unsigned int g_Xeh[(size_t)N_EDGES * (D/2)];// fp16 Xe
__device__ int g_cnt[T_CNT];
__device__ int g_off[T_CNT + 1];
__device__ int g_cur[T_CNT];
__device__ int g_bsum[SCAN_NB];
__device__ int g_list[2 * MAX_NNZ];

// ---------------------------------------------------------------------------
// CSR build
// ---------------------------------------------------------------------------
__global__ void zero_cnt_kernel() {
    int i = blockIdx.x * blockDim.x + threadIdx.x;
    if (i < T_CNT) g_cnt[i] = 0;
}

__global__ __launch_bounds__(256) void hist_kernel(
    const int* __restrict__ vertex, const int* __restrict__ edges, int nnz)
{
    int i = blockIdx.x * blockDim.x + threadIdx.x;
    if (i >= nnz) return;
    atomicAdd(&g_cnt[edges[i]], 1);
    atomicAdd(&g_cnt[N_EDGES + vertex[i]], 1);
}

__global__ __launch_bounds__(1024) void scan1_kernel() {
    int b = blockIdx.x;
    int i = b * SCAN_CHUNK + threadIdx.x;
    int v = (i < T_CNT) ? g_cnt[i] : 0;
    int lane = threadIdx.x & 31, wid = threadIdx.x >> 5;
    int x = v;
#pragma unroll
    for (int o = 1; o < 32; o <<= 1) {
        int y = __shfl_up_sync(0xffffffffu, x, o);
        if (lane >= o) x += y;
    }
    __shared__ int wsum[32];
    if (lane == 31) wsum[wid] = x;
    __syncthreads();
    if (wid == 0) {
        int w = wsum[lane];
#pragma unroll
        for (int o = 1; o < 32; o <<= 1) {
            int y = __shfl_up_sync(0xffffffffu, w, o);
            if (lane >= o) w += y;
        }
        wsum[lane] = w;
    }
    __syncthreads();
    int base = (wid > 0) ? wsum[wid - 1] : 0;
    int incl = x + base;
    if (i < T_CNT) g_off[i] = incl - v;
    if (threadIdx.x == SCAN_CHUNK - 1) g_bsum[b] = incl;
}

__global__ __launch_bounds__(256) void scan2_kernel() {
    __shared__ int s[256];
    int t = threadIdx.x;
    int v = (t < SCAN_NB) ? g_bsum[t] : 0;
    s[t] = v;
    __syncthreads();
    for (int o = 1; o < 256; o <<= 1) {
        int y = (t >= o) ? s[t - o] : 0;
        __syncthreads();
        s[t] += y;
        __syncthreads();
    }
    if (t < SCAN_NB) g_bsum[t] = s[t] - v;
}

__global__ __launch_bounds__(1024) void scan3_kernel(int total) {
    int i = blockIdx.x * SCAN_CHUNK + threadIdx.x;
    if (i < T_CNT) {
        int o = g_off[i] + g_bsum[blockIdx.x];
        g_off[i] = o;
        g_cur[i] = o;
    }
    if (i == 0) g_off[T_CNT] = total;
}

__global__ __launch_bounds__(256) void fill_kernel(
    const int* __restrict__ vertex, const int* __restrict__ edges, int nnz)
{
    int i = blockIdx.x * blockDim.x + threadIdx.x;
    if (i >= nnz) return;
    int e = edges[i], v = vertex[i];
    int p = atomicAdd(&g_cur[e], 1);
    g_list[p] = v;
    int q = atomicAdd(&g_cur[N_EDGES + v], 1);
    g_list[q] = e;
}

// ---------------------------------------------------------------------------
// GEMM: Xp = X @ W  (fp32 via packed fma.rn.f32x2; epilogue writes fp32+fp16)
// ---------------------------------------------------------------------------
#define BM 128
#define BN 128
#define BK 16

__device__ __forceinline__ unsigned long long pack_f32x2(float lo, float hi) {
    unsigned long long r;
    asm("mov.b64 %0, {%1, %2};" : "=l"(r) : "f"(lo), "f"(hi));
    return r;
}

__global__ __launch_bounds__(256) void gemm_kernel(
    const float* __restrict__ X, const float* __restrict__ W, int M)
{
    __shared__ float As[BK][BM + 4];
    __shared__ float Bs[BK][BN];

    int tid = threadIdx.x;
    int tx = tid & 15;
    int ty = tid >> 4;
    int row0 = blockIdx.x * BM;

    unsigned long long acc2[8][4];   // 8 rows x 4 packed col-pairs
#pragma unroll
    for (int i = 0; i < 8; i++)
#pragma unroll
        for (int j = 0; j < 4; j++) acc2[i][j] = 0ull;

    for (int k0 = 0; k0 < D; k0 += BK) {
#pragma unroll
        for (int l = 0; l < 2; l++) {
            int idx = tid * 2 + l;
            int m   = idx >> 2;
            int kq  = (idx & 3) * 4;
            int gm  = row0 + m;
            float4 av = (gm < M) ? *(const float4*)(X + (size_t)gm * D + k0 + kq)
                                 : make_float4(0.f, 0.f, 0.f, 0.f);
            As[kq + 0][m] = av.x;
            As[kq + 1][m] = av.y;
            As[kq + 2][m] = av.z;
            As[kq + 3][m] = av.w;
        }
#pragma unroll
        for (int l = 0; l < 2; l++) {
            int idx = tid * 2 + l;
            int kr  = idx >> 5;
            int n4  = (idx & 31) * 4;
            *(float4*)&Bs[kr][n4] = *(const float4*)(W + (size_t)(k0 + kr) * D + n4);
        }
        __syncthreads();

#pragma unroll
        for (int k = 0; k < BK; k++) {
            float a[8];
            *(float4*)(a + 0) = *(const float4*)&As[k][ty * 8 + 0];
            *(float4*)(a + 4) = *(const float4*)&As[k][ty * 8 + 4];
            float b[8];
            *(float4*)(b + 0) = *(const float4*)&Bs[k][tx * 8 + 0];
            *(float4*)(b + 4) = *(const float4*)&Bs[k][tx * 8 + 4];
            unsigned long long b2[4];
#pragma unroll
            for (int j = 0; j < 4; j++) b2[j] = pack_f32x2(b[2*j], b[2*j+1]);
#pragma unroll
            for (int i = 0; i < 8; i++) {
                unsigned long long a2 = pack_f32x2(a[i], a[i]);
#pragma unroll
                for (int j = 0; j < 4; j++)
                    asm("fma.rn.f32x2 %0, %1, %2, %0;"
                        : "+l"(acc2[i][j]) : "l"(a2), "l"(b2[j]));
            }
        }
        __syncthreads();
    }

#pragma unroll
    for (int i = 0; i < 8; i++) {
        int gm = row0 + ty * 8 + i;
        if (gm < M) {
            float c[8];
#pragma unroll
            for (int j = 0; j < 4; j++)
                asm("mov.b64 {%0, %1}, %2;" : "=f"(c[2*j]), "=f"(c[2*j+1]) : "l"(acc2[i][j]));
            float* p = g_Xp + (size_t)gm * D + tx * 8;
            *(float4*)(p + 0) = make_float4(c[0], c[1], c[2], c[3]);
            *(float4*)(p + 4) = make_float4(c[4], c[5], c[6], c[7]);
            // fp16 copy for gather pass 1
            unsigned int h[4];
#pragma unroll
            for (int j = 0; j < 4; j++) {
                __half2 hv = __float22half2_rn(make_float2(c[2*j], c[2*j+1]));
                h[j] = *(unsigned int*)&hv;
            }
            *(uint4*)(g_Xph + (size_t)gm * (D/2) + tx * 4) = make_uint4(h[0], h[1], h[2], h[3]);
        }
    }
}

// ---------------------------------------------------------------------------
// Warp segment sum over fp16 rows (row stride = 32 uint2 = 256B), fp32 acc
// ---------------------------------------------------------------------------
__device__ __forceinline__ void acc_row_h(
    const uint2* __restrict__ src, int r, int lane, float4& acc)
{
    uint2 hv = __ldg(src + (size_t)r * 32 + lane);
    float2 f0 = __half22float2(*(const __half2*)&hv.x);
    float2 f1 = __half22float2(*(const __half2*)&hv.y);
    acc.x += f0.x; acc.y += f0.y; acc.z += f1.x; acc.w += f1.y;
}

__device__ __forceinline__ void warp_segment_sum_h(
    const uint2* __restrict__ src, int start, int end, int lane, float4& acc)
{
    for (int j = start; j < end; j += 32) {
        int n = end - j;
        int cnt = n < 32 ? n : 32;
        int idx = (lane < cnt) ? __ldg(g_list + j + lane) : 0;
        int t = 0;
        for (; t + 8 <= cnt; t += 8) {
#pragma unroll
            for (int u = 0; u < 8; u++) {
                int r = __shfl_sync(0xffffffffu, idx, t + u);
                acc_row_h(src, r, lane, acc);
            }
        }
        for (; t < cnt; t++) {
            int r = __shfl_sync(0xffffffffu, idx, t);
            acc_row_h(src, r, lane, acc);
        }
    }
}

// ---------------------------------------------------------------------------
// Pass 1: Xe[e] = sum of incident Xp rows  (warp per edge, fp16 in/out)
// ---------------------------------------------------------------------------
__global__ __launch_bounds__(256) void gather_edge_kernel() {
    int warp = (blockIdx.x * blockDim.x + threadIdx.x) >> 5;
    if (warp >= N_EDGES) return;
    int lane = threadIdx.x & 31;
    int start = g_off[warp];
    int end   = g_off[warp + 1];
    float4 acc = make_float4(0.f, 0.f, 0.f, 0.f);
    warp_segment_sum_h((const uint2*)g_Xph, start, end, lane, acc);
    __half2 h0 = __float22half2_rn(make_float2(acc.x, acc.y));
    __half2 h1 = __float22half2_rn(make_float2(acc.z, acc.w));
    uint2 o = make_uint2(*(unsigned int*)&h0, *(unsigned int*)&h1);
    ((uint2*)g_Xeh)[(size_t)warp * 32 + lane] = o;
}

// ---------------------------------------------------------------------------
// Pass 2: out[v] = gelu((1+eps)*Xp[v] + sum of incident Xe rows)
// ---------------------------------------------------------------------------
__device__ __forceinline__ float gelu_exact(float x) {
    return 0.5f * x * (1.0f + erff(x * 0.70710678118654752440f));
}

__global__ __launch_bounds__(256) void gather_node_kernel(
    float* __restrict__ out, const float* __restrict__ eps, int M)
{
    int warp = (blockIdx.x * blockDim.x + threadIdx.x) >> 5;
    if (warp >= M) return;
    int lane = threadIdx.x & 31;
    int start = g_off[N_EDGES + warp];
    int end   = g_off[N_EDGES + warp + 1];
    float4 acc = make_float4(0.f, 0.f, 0.f, 0.f);
    warp_segment_sum_h((const uint2*)g_Xeh, start, end, lane, acc);

    float s = 1.0f + __ldg(eps);
    float4 p = __ldg((const float4*)g_Xp + (size_t)warp * 32 + lane);
    float4 r;
    r.x = gelu_exact(fmaf(s, p.x, acc.x));
    r.y = gelu_exact(fmaf(s, p.y, acc.y));
    r.z = gelu_exact(fmaf(s, p.z, acc.z));
    r.w = gelu_exact(fmaf(s, p.w, acc.w));
    ((float4*)out)[(size_t)warp * 32 + lane] = r;
}

// ---------------------------------------------------------------------------
// Launch
// ---------------------------------------------------------------------------
extern "C" void kernel_launch(void* const* d_in, const int* in_sizes, int n_in,
                              void* d_out, int out_size)
{
    const float* X      = (const float*)d_in[0];
    const float* W      = (const float*)d_in[1];
    const float* eps    = (const float*)d_in[2];
    const int*   vertex = (const int*)d_in[3];
    const int*   edges  = (const int*)d_in[4];
    float*       out    = (float*)d_out;

    int nnz = in_sizes[3];
    int M   = in_sizes[0] / D;

    zero_cnt_kernel<<<(T_CNT + 255) / 256, 256>>>();
    hist_kernel<<<(nnz + 255) / 256, 256>>>(vertex, edges, nnz);
    scan1_kernel<<<SCAN_NB, SCAN_CHUNK>>>();
    scan2_kernel<<<1, 256>>>();
    scan3_kernel<<<SCAN_NB, SCAN_CHUNK>>>(2 * nnz);
    fill_kernel<<<(nnz + 255) / 256, 256>>>(vertex, edges, nnz);

    gemm_kernel<<<(M + BM - 1) / BM, 256>>>(X, W, M);

    gather_edge_kernel<<<(N_EDGES * 32 + 255) / 256, 256>>>();
    gather_node_kernel<<<(M * 32 + 255) / 256, 256>>>(out, eps, M);
}

// round 6
// speedup vs baseline: 2.2769x; 1.2114x over previous
#include <cuda_runtime.h>
#include <cuda_fp16.h>
#include <math.h>
#include <cstdint>

#define N_NODES 100000
#define N_EDGES 50000
#define D 128
#define MAX_NNZ 1600000
#define T_CNT (N_EDGES + N_NODES)
#define SCAN_CHUNK 1024
#define SCAN_NB ((T_CNT + SCAN_CHUNK - 1) / SCAN_CHUNK)

// ---------------------------------------------------------------------------
// Device-global scratch
// ---------------------------------------------------------------------------
__device__ float        g_Xp [(size_t)N_NODES * D];      // fp32 Xp (combine)
__device__ unsigned int g_Xph[(size_t)N_NODES * (D/2)];  // fp16 Xp (gather src)
__device__ unsigned int g_Xeh[(size_t)N_EDGES * (D/2)];  // fp16 Xe
__device__ int g_cnt[T_CNT];
__device__ int g_off[T_CNT + 1];
__device__ int g_cur[T_CNT];
__device__ int g_bsum[SCAN_NB];
__device__ int g_list[2 * MAX_NNZ];

// ---------------------------------------------------------------------------
// CSR build
// ---------------------------------------------------------------------------
__global__ void zero_cnt_kernel() {
    int i = blockIdx.x * blockDim.x + threadIdx.x;
    if (i < T_CNT) g_cnt[i] = 0;
}

__global__ __launch_bounds__(256) void hist_kernel(
    const int* __restrict__ vertex, const int* __restrict__ edges, int nnz)
{
    int i = blockIdx.x * blockDim.x + threadIdx.x;
    if (i >= nnz) return;
    atomicAdd(&g_cnt[edges[i]], 1);
    atomicAdd(&g_cnt[N_EDGES + vertex[i]], 1);
}

__global__ __launch_bounds__(1024) void scan1_kernel() {
    int b = blockIdx.x;
    int i = b * SCAN_CHUNK + threadIdx.x;
    int v = (i < T_CNT) ? g_cnt[i] : 0;
    int lane = threadIdx.x & 31, wid = threadIdx.x >> 5;
    int x = v;
#pragma unroll
    for (int o = 1; o < 32; o <<= 1) {
        int y = __shfl_up_sync(0xffffffffu, x, o);
        if (lane >= o) x += y;
    }
    __shared__ int wsum[32];
    if (lane == 31) wsum[wid] = x;
    __syncthreads();
    if (wid == 0) {
        int w = wsum[lane];
#pragma unroll
        for (int o = 1; o < 32; o <<= 1) {
            int y = __shfl_up_sync(0xffffffffu, w, o);
            if (lane >= o) w += y;
        }
        wsum[lane] = w;
    }
    __syncthreads();
    int base = (wid > 0) ? wsum[wid - 1] : 0;
    int incl = x + base;
    if (i < T_CNT) g_off[i] = incl - v;
    if (threadIdx.x == SCAN_CHUNK - 1) g_bsum[b] = incl;
}

__global__ __launch_bounds__(256) void scan2_kernel() {
    __shared__ int s[256];
    int t = threadIdx.x;
    int v = (t < SCAN_NB) ? g_bsum[t] : 0;
    s[t] = v;
    __syncthreads();
    for (int o = 1; o < 256; o <<= 1) {
        int y = (t >= o) ? s[t - o] : 0;
        __syncthreads();
        s[t] += y;
        __syncthreads();
    }
    if (t < SCAN_NB) g_bsum[t] = s[t] - v;
}

__global__ __launch_bounds__(1024) void scan3_kernel(int total) {
    int i = blockIdx.x * SCAN_CHUNK + threadIdx.x;
    if (i < T_CNT) {
        int o = g_off[i] + g_bsum[blockIdx.x];
        g_off[i] = o;
        g_cur[i] = o;
    }
    if (i == 0) g_off[T_CNT] = total;
}

__global__ __launch_bounds__(256) void fill_kernel(
    const int* __restrict__ vertex, const int* __restrict__ edges, int nnz)
{
    int i = blockIdx.x * blockDim.x + threadIdx.x;
    if (i >= nnz) return;
    int e = edges[i], v = vertex[i];
    int p = atomicAdd(&g_cur[e], 1);
    g_list[p] = v;
    int q = atomicAdd(&g_cur[N_EDGES + v], 1);
    g_list[q] = e;
}

// ---------------------------------------------------------------------------
// TF32 mma.sync GEMM: Xp = X @ W  (persistent, W resident in SMEM)
//   256 threads = 8 warps; warp w computes rows [w*16, w*16+16) x 128 cols.
//   mma.m16n8k8.row.col.f32.tf32.tf32.f32
// ---------------------------------------------------------------------------
#define AP 132          // As row pitch (floats): A-frag LDS conflict-free
#define BP 136          // Bs row pitch (floats): B-frag LDS conflict-free
#define GEMM_SMEM ((128 * AP + 128 * BP) * 4)

__device__ __forceinline__ float cvt_tf32(float x) {
    float r;
    asm("cvt.rn.tf32.f32 %0, %1;" : "=f"(r) : "f"(x));
    return r;
}

__global__ __launch_bounds__(256) void gemm_kernel(
    const float* __restrict__ X, const float* __restrict__ W, int M)
{
    extern __shared__ float smem[];
    float* As = smem;                 // [128][AP]
    float* Bs = smem + 128 * AP;      // [128][BP]

    int tid  = threadIdx.x;
    int wid  = tid >> 5;
    int lane = tid & 31;
    int gid  = lane >> 2;             // 0..7
    int tig  = lane & 3;              // 0..3

    // Load W (k-major [128][128]) into Bs once, tf32-rounded
    for (int i = tid; i < 128 * 32; i += 256) {
        int k  = i >> 5;
        int c4 = (i & 31) << 2;
        float4 v = *(const float4*)(W + (size_t)k * D + c4);
        v.x = cvt_tf32(v.x); v.y = cvt_tf32(v.y);
        v.z = cvt_tf32(v.z); v.w = cvt_tf32(v.w);
        *(float4*)&Bs[k * BP + c4] = v;
    }

    int n_tiles = (M + 127) >> 7;
    int mrow = wid * 16;

    for (int tile = blockIdx.x; tile < n_tiles; tile += gridDim.x) {
        int row0 = tile << 7;

        // Load A tile [128][128], tf32-rounded
        for (int i = tid; i < 128 * 32; i += 256) {
            int m  = i >> 5;
            int c4 = (i & 31) << 2;
            int gm = row0 + m;
            if (gm >= M) gm = M - 1;
            float4 v = *(const float4*)(X + (size_t)gm * D + c4);
            v.x = cvt_tf32(v.x); v.y = cvt_tf32(v.y);
            v.z = cvt_tf32(v.z); v.w = cvt_tf32(v.w);
            *(float4*)&As[m * AP + c4] = v;
        }
        __syncthreads();

        float acc[16][4];
#pragma unroll
        for (int nt = 0; nt < 16; nt++)
#pragma unroll
            for (int q = 0; q < 4; q++) acc[nt][q] = 0.f;

#pragma unroll
        for (int ks = 0; ks < 16; ks++) {
            int k = ks << 3;
            uint32_t a0 = __float_as_uint(As[(mrow + gid)     * AP + k + tig]);
            uint32_t a1 = __float_as_uint(As[(mrow + gid + 8) * AP + k + tig]);
            uint32_t a2 = __float_as_uint(As[(mrow + gid)     * AP + k + tig + 4]);
            uint32_t a3 = __float_as_uint(As[(mrow + gid + 8) * AP + k + tig + 4]);
#pragma unroll
            for (int nt = 0; nt < 16; nt++) {
                uint32_t b0 = __float_as_uint(Bs[(k + tig)     * BP + nt * 8 + gid]);
                uint32_t b1 = __float_as_uint(Bs[(k + tig + 4) * BP + nt * 8 + gid]);
                asm volatile(
                    "mma.sync.aligned.m16n8k8.row.col.f32.tf32.tf32.f32 "
                    "{%0,%1,%2,%3}, {%4,%5,%6,%7}, {%8,%9}, {%0,%1,%2,%3};"
                    : "+f"(acc[nt][0]), "+f"(acc[nt][1]), "+f"(acc[nt][2]), "+f"(acc[nt][3])
                    : "r"(a0), "r"(a1), "r"(a2), "r"(a3), "r"(b0), "r"(b1));
            }
        }
        __syncthreads();

        // Epilogue: c0,c1 -> row gm0 cols nt*8+tig*2; c2,c3 -> row gm0+8
        int gm0 = row0 + mrow + gid;
        int gm1 = gm0 + 8;
        bool v0 = gm0 < M, v1 = gm1 < M;
#pragma unroll
        for (int nt = 0; nt < 16; nt++) {
            int col = nt * 8 + tig * 2;
            if (v0) {
                *(float2*)(g_Xp + (size_t)gm0 * D + col) = make_float2(acc[nt][0], acc[nt][1]);
                __half2 h = __float22half2_rn(make_float2(acc[nt][0], acc[nt][1]));
                g_Xph[(size_t)gm0 * (D/2) + (col >> 1)] = *(unsigned int*)&h;
            }
            if (v1) {
                *(float2*)(g_Xp + (size_t)gm1 * D + col) = make_float2(acc[nt][2], acc[nt][3]);
                __half2 h = __float22half2_rn(make_float2(acc[nt][2], acc[nt][3]));
                g_Xph[(size_t)gm1 * (D/2) + (col >> 1)] = *(unsigned int*)&h;
            }
        }
    }
}

// ---------------------------------------------------------------------------
// Warp segment sum over fp16 rows (row = 256B), fp32 accumulate
// ---------------------------------------------------------------------------
__device__ __forceinline__ void acc_row_h(
    const uint2* __restrict__ src, int r, int lane, float4& acc)
{
    uint2 hv = __ldg(src + (size_t)r * 32 + lane);
    float2 f0 = __half22float2(*(const __half2*)&hv.x);
    float2 f1 = __half22float2(*(const __half2*)&hv.y);
    acc.x += f0.x; acc.y += f0.y; acc.z += f1.x; acc.w += f1.y;
}

__device__ __forceinline__ void warp_segment_sum_h(
    const uint2* __restrict__ src, int start, int end, int lane, float4& acc)
{
    for (int j = start; j < end; j += 32) {
        int n = end - j;
        int cnt = n < 32 ? n : 32;
        int idx = (lane < cnt) ? __ldg(g_list + j + lane) : 0;
        int t = 0;
        for (; t + 8 <= cnt; t += 8) {
#pragma unroll
            for (int u = 0; u < 8; u++) {
                int r = __shfl_sync(0xffffffffu, idx, t + u);
                acc_row_h(src, r, lane, acc);
            }
        }
        for (; t < cnt; t++) {
            int r = __shfl_sync(0xffffffffu, idx, t);
            acc_row_h(src, r, lane, acc);
        }
    }
}

__global__ __launch_bounds__(256) void gather_edge_kernel() {
    int warp = (blockIdx.x * blockDim.x + threadIdx.x) >> 5;
    if (warp >= N_EDGES) return;
    int lane = threadIdx.x & 31;
    int start = g_off[warp];
    int end   = g_off[warp + 1];
    float4 acc = make_float4(0.f, 0.f, 0.f, 0.f);
    warp_segment_sum_h((const uint2*)g_Xph, start, end, lane, acc);
    __half2 h0 = __float22half2_rn(make_float2(acc.x, acc.y));
    __half2 h1 = __float22half2_rn(make_float2(acc.z, acc.w));
    uint2 o = make_uint2(*(unsigned int*)&h0, *(unsigned int*)&h1);
    ((uint2*)g_Xeh)[(size_t)warp * 32 + lane] = o;
}

__device__ __forceinline__ float gelu_exact(float x) {
    return 0.5f * x * (1.0f + erff(x * 0.70710678118654752440f));
}

__global__ __launch_bounds__(256) void gather_node_kernel(
    float* __restrict__ out, const float* __restrict__ eps, int M)
{
    int warp = (blockIdx.x * blockDim.x + threadIdx.x) >> 5;
    if (warp >= M) return;
    int lane = threadIdx.x & 31;
    int start = g_off[N_EDGES + warp];
    int end   = g_off[N_EDGES + warp + 1];
    float4 acc = make_float4(0.f, 0.f, 0.f, 0.f);
    warp_segment_sum_h((const uint2*)g_Xeh, start, end, lane, acc);

    float s = 1.0f + __ldg(eps);
    float4 p = __ldg((const float4*)g_Xp + (size_t)warp * 32 + lane);
    float4 r;
    r.x = gelu_exact(fmaf(s, p.x, acc.x));
    r.y = gelu_exact(fmaf(s, p.y, acc.y));
    r.z = gelu_exact(fmaf(s, p.z, acc.z));
    r.w = gelu_exact(fmaf(s, p.w, acc.w));
    ((float4*)out)[(size_t)warp * 32 + lane] = r;
}

// ---------------------------------------------------------------------------
// Launch: GEMM on a forked stream, CSR build on the capture stream, join
// before the gathers. Statics are created on the (uncaptured) correctness
// call and reused during capture.
// ---------------------------------------------------------------------------
extern "C" void kernel_launch(void* const* d_in, const int* in_sizes, int n_in,
                              void* d_out, int out_size)
{
    const float* X      = (const float*)d_in[0];
    const float* W      = (const float*)d_in[1];
    const float* eps    = (const float*)d_in[2];
    const int*   vertex = (const int*)d_in[3];
    const int*   edges  = (const int*)d_in[4];
    float*       out    = (float*)d_out;

    int nnz = in_sizes[3];
    int M   = in_sizes[0] / D;

    static cudaStream_t s_gemm = nullptr;
    static cudaEvent_t  e_fork = nullptr, e_gemm = nullptr;
    if (!s_gemm) {
        cudaStreamCreateWithFlags(&s_gemm, cudaStreamNonBlocking);
        cudaEventCreateWithFlags(&e_fork, cudaEventDisableTiming);
        cudaEventCreateWithFlags(&e_gemm, cudaEventDisableTiming);
        cudaFuncSetAttribute(gemm_kernel,
                             cudaFuncAttributeMaxDynamicSharedMemorySize, GEMM_SMEM);
    }

    // Fork: GEMM runs concurrently with the CSR build.
    cudaEventRecord(e_fork, 0);
    cudaStreamWaitEvent(s_gemm, e_fork, 0);
    gemm_kernel<<<148, 256, GEMM_SMEM, s_gemm>>>(X, W, M);
    cudaEventRecord(e_gemm, s_gemm);

    // CSR build on the capture (default) stream.
    zero_cnt_kernel<<<(T_CNT + 255) / 256, 256>>>();
    hist_kernel<<<(nnz + 255) / 256, 256>>>(vertex, edges, nnz);
    scan1_kernel<<<SCAN_NB, SCAN_CHUNK>>>();
    scan2_kernel<<<1, 256>>>();
    scan3_kernel<<<SCAN_NB, SCAN_CHUNK>>>(2 * nnz);
    fill_kernel<<<(nnz + 255) / 256, 256>>>(vertex, edges, nnz);

    // Join, then the two gather passes.
    cudaStreamWaitEvent(0, e_gemm, 0);
    gather_edge_kernel<<<(N_EDGES * 32 + 255) / 256, 256>>>();
    gather_node_kernel<<<(M * 32 + 255) / 256, 256>>>(out, eps, M);
}